// round 2
// baseline (speedup 1.0000x reference)
#include <cuda_runtime.h>
#include <cstdint>

// Problem constants
#define NT_   128      // N*T = 4*32
#define V_    1024
#define CIN_  256
#define COUT_ 64

// Scratch: theta/phi projections, fp32. 33.5 MB each (allowed: __device__ globals).
__device__ float g_theta[NT_ * V_ * COUT_];
__device__ float g_phi[NT_ * V_ * COUT_];

__device__ __forceinline__ unsigned f2tf(float x) {
    unsigned u;
    asm("cvt.rna.tf32.f32 %0, %1;" : "=r"(u) : "f"(x));
    return u;
}

__device__ __forceinline__ void mma_tf32(float& c0, float& c1, float& c2, float& c3,
                                         unsigned a0, unsigned a1, unsigned a2, unsigned a3,
                                         unsigned b0, unsigned b1) {
    asm volatile(
        "mma.sync.aligned.m16n8k8.row.col.f32.tf32.tf32.f32 "
        "{%0,%1,%2,%3},{%4,%5,%6,%7},{%8,%9},{%0,%1,%2,%3};\n"
        : "+f"(c0), "+f"(c1), "+f"(c2), "+f"(c3)
        : "r"(a0), "r"(a1), "r"(a2), "r"(a3), "r"(b0), "r"(b1));
}

// ============================================================================
// Kernel 1: projection. Per block: out[64 rows of v][128 cols] where cols
// 0..63 = theta, 64..127 = phi.  C = z_tile[64,256] @ Wcat^T  (Wcat [128,256]).
// tf32 mma m16n8k8, fp32 accumulate. Grid: (V/64, NT).
// ============================================================================
__global__ __launch_bounds__(256) void proj_kernel(
    const float* __restrict__ z, const float* __restrict__ tw,
    const float* __restrict__ tb, const float* __restrict__ pw,
    const float* __restrict__ pb)
{
    __shared__ unsigned As[64 * 36];    // 64 rows x 32 k, stride 36 (conflict-free frags)
    __shared__ unsigned Bs[128 * 36];   // 128 rows (n) x 32 k
    __shared__ float bias_s[128];

    const int tid = threadIdx.x;
    const int nt = blockIdx.y;
    const int vbase = blockIdx.x * 64;

    if (tid < 128) bias_s[tid] = (tid < 64) ? tb[tid] : pb[tid - 64];

    const int wid = tid >> 5, lane = tid & 31;
    const int g = lane >> 2, t = lane & 3;
    const int wm = wid & 3;     // 4 m-warps of 16 rows
    const int wn = wid >> 2;    // 2 n-warps of 64 cols

    float acc[8][4];
    #pragma unroll
    for (int i = 0; i < 8; i++)
        #pragma unroll
        for (int j = 0; j < 4; j++) acc[i][j] = 0.f;

    const float* zb = z + (size_t)(nt * V_ + vbase) * CIN_;

    for (int kc = 0; kc < CIN_; kc += 32) {
        // Load A tile 64x32 (2 float4 per thread)
        {
            int r = tid >> 3, c4 = (tid & 7) * 4;
            #pragma unroll
            for (int p = 0; p < 2; p++) {
                float4 v = *(const float4*)(zb + (size_t)(r + 32 * p) * CIN_ + kc + c4);
                unsigned* d = &As[(r + 32 * p) * 36 + c4];
                d[0] = f2tf(v.x); d[1] = f2tf(v.y); d[2] = f2tf(v.z); d[3] = f2tf(v.w);
            }
            // Load B tile 128x32 (theta_w rows 0..63, phi_w rows 64..127)
            #pragma unroll
            for (int p = 0; p < 4; p++) {
                int rr = (tid >> 3) + 32 * p;
                const float* src = (rr < 64) ? (tw + (size_t)rr * CIN_)
                                             : (pw + (size_t)(rr - 64) * CIN_);
                float4 v = *(const float4*)(src + kc + c4);
                unsigned* d = &Bs[rr * 36 + c4];
                d[0] = f2tf(v.x); d[1] = f2tf(v.y); d[2] = f2tf(v.z); d[3] = f2tf(v.w);
            }
        }
        __syncthreads();

        #pragma unroll
        for (int ks = 0; ks < 4; ks++) {
            const int k8 = ks * 8;
            unsigned a0 = As[(wm * 16 + g) * 36 + k8 + t];
            unsigned a1 = As[(wm * 16 + g + 8) * 36 + k8 + t];
            unsigned a2 = As[(wm * 16 + g) * 36 + k8 + t + 4];
            unsigned a3 = As[(wm * 16 + g + 8) * 36 + k8 + t + 4];
            #pragma unroll
            for (int nf = 0; nf < 8; nf++) {
                int br = wn * 64 + nf * 8 + g;
                unsigned b0 = Bs[br * 36 + k8 + t];
                unsigned b1 = Bs[br * 36 + k8 + t + 4];
                mma_tf32(acc[nf][0], acc[nf][1], acc[nf][2], acc[nf][3],
                         a0, a1, a2, a3, b0, b1);
            }
        }
        __syncthreads();
    }

    // Epilogue: add bias, write to theta/phi scratch
    const int row0 = vbase + wm * 16 + g;
    #pragma unroll
    for (int nf = 0; nf < 8; nf++) {
        int col = wn * 64 + nf * 8 + 2 * t;   // 0..127, theta/phi split at 64
        float b0v = bias_s[col], b1v = bias_s[col + 1];
        float* dst = (col < 64) ? g_theta : g_phi;
        int c = (col < 64) ? col : col - 64;
        float2 v0 = make_float2(acc[nf][0] + b0v, acc[nf][1] + b1v);
        float2 v1 = make_float2(acc[nf][2] + b0v, acc[nf][3] + b1v);
        *(float2*)&dst[((size_t)(nt * V_) + row0) * COUT_ + c] = v0;
        *(float2*)&dst[((size_t)(nt * V_) + row0 + 8) * COUT_ + c] = v1;
    }
}

// ============================================================================
// Kernel 2: S = theta_tile[32,64] @ phi^T[64,1024] -> SMEM -> softmax -> G.
// Grid: NT*32 blocks (32 rows each), 256 threads (8 warps).
// SMEM: Ts (tf32 theta tile), Ps[2] (double-buffered phi chunks of 128 rows),
//       Sbuf 32x1032 fp32 (full softmax rows resident).
// ============================================================================
#define TS_ELEMS   (32 * 68)
#define PS_ELEMS   (128 * 68)
#define SBUF_STRIDE 1032
#define SMEM2_BYTES ((TS_ELEMS + 2 * PS_ELEMS) * 4 + 32 * SBUF_STRIDE * 4)

__global__ __launch_bounds__(256, 1) void adj_kernel(float* __restrict__ G)
{
    extern __shared__ unsigned smem[];
    unsigned* Ts = smem;                               // 32 x 64, stride 68
    unsigned* Ps = smem + TS_ELEMS;                    // 2 x (128 x 64, stride 68)
    float* Sbuf = (float*)(smem + TS_ELEMS + 2 * PS_ELEMS);  // 32 x 1024, stride 1032

    const int tid = threadIdx.x, lane = tid & 31, wid = tid >> 5;
    const int g = lane >> 2, t = lane & 3;
    const int bx = blockIdx.x;
    const int nt = bx >> 5;
    const int vbase = (bx & 31) * 32;

    const float* th = g_theta + (size_t)(nt * V_ + vbase) * COUT_;
    const float* ph = g_phi + (size_t)nt * V_ * COUT_;

    // Load theta tile 32x64 -> Ts (tf32)
    {
        int r = tid >> 4, c4 = (tid & 15) * 4;
        #pragma unroll
        for (int p = 0; p < 2; p++) {
            float4 v = *(const float4*)(th + (size_t)(r + 16 * p) * COUT_ + c4);
            unsigned* d = &Ts[(r + 16 * p) * 68 + c4];
            d[0] = f2tf(v.x); d[1] = f2tf(v.y); d[2] = f2tf(v.z); d[3] = f2tf(v.w);
        }
    }
    // Load phi chunk 0 -> Ps[0]
    {
        int rb = tid >> 4, c4 = (tid & 15) * 4;
        #pragma unroll
        for (int p = 0; p < 8; p++) {
            int r = rb + 16 * p;
            float4 v = *(const float4*)(ph + (size_t)r * COUT_ + c4);
            unsigned* d = &Ps[r * 68 + c4];
            d[0] = f2tf(v.x); d[1] = f2tf(v.y); d[2] = f2tf(v.z); d[3] = f2tf(v.w);
        }
    }
    __syncthreads();

    const int wm = wid & 1;    // 2 m-warps x 16 rows
    const int wn = wid >> 1;   // 4 n-warps x 32 cols

    for (int cw = 0; cw < 8; cw++) {
        // Prefetch next phi chunk into registers
        float4 pre[8];
        const int rb = tid >> 4, c4 = (tid & 15) * 4;
        if (cw < 7) {
            const int wbn = (cw + 1) * 128;
            #pragma unroll
            for (int p = 0; p < 8; p++)
                pre[p] = *(const float4*)(ph + (size_t)(wbn + rb + 16 * p) * COUT_ + c4);
        }

        // Compute S[32,128] for this chunk from Ps[cw&1]
        unsigned* P = Ps + (cw & 1) * PS_ELEMS;
        float acc[4][4];
        #pragma unroll
        for (int i = 0; i < 4; i++)
            #pragma unroll
            for (int j = 0; j < 4; j++) acc[i][j] = 0.f;

        #pragma unroll
        for (int ks = 0; ks < 8; ks++) {
            const int k8 = ks * 8;
            unsigned a0 = Ts[(wm * 16 + g) * 68 + k8 + t];
            unsigned a1 = Ts[(wm * 16 + g + 8) * 68 + k8 + t];
            unsigned a2 = Ts[(wm * 16 + g) * 68 + k8 + t + 4];
            unsigned a3 = Ts[(wm * 16 + g + 8) * 68 + k8 + t + 4];
            #pragma unroll
            for (int nf = 0; nf < 4; nf++) {
                int br = wn * 32 + nf * 8 + g;
                unsigned b0 = P[br * 68 + k8 + t];
                unsigned b1 = P[br * 68 + k8 + t + 4];
                mma_tf32(acc[nf][0], acc[nf][1], acc[nf][2], acc[nf][3],
                         a0, a1, a2, a3, b0, b1);
            }
        }

        // Scatter acc into Sbuf
        const int row0 = wm * 16 + g;
        #pragma unroll
        for (int nf = 0; nf < 4; nf++) {
            int col = cw * 128 + wn * 32 + nf * 8 + 2 * t;
            *(float2*)&Sbuf[row0 * SBUF_STRIDE + col] = make_float2(acc[nf][0], acc[nf][1]);
            *(float2*)&Sbuf[(row0 + 8) * SBUF_STRIDE + col] = make_float2(acc[nf][2], acc[nf][3]);
        }

        // Commit prefetched chunk to the other buffer
        if (cw < 7) {
            unsigned* Pn = Ps + ((cw + 1) & 1) * PS_ELEMS;
            #pragma unroll
            for (int p = 0; p < 8; p++) {
                unsigned* d = &Pn[(rb + 16 * p) * 68 + c4];
                d[0] = f2tf(pre[p].x); d[1] = f2tf(pre[p].y);
                d[2] = f2tf(pre[p].z); d[3] = f2tf(pre[p].w);
            }
        }
        __syncthreads();
    }

    // Fused softmax: warp w handles rows {w, w+8, w+16, w+24}; lane l owns
    // cols l + 32*i (coalesced gmem writes, conflict-free smem reads).
    #pragma unroll 1
    for (int rr = 0; rr < 4; rr++) {
        const int row = wid + rr * 8;
        const float* sp = &Sbuf[row * SBUF_STRIDE + lane];
        float x[32];
        #pragma unroll
        for (int i = 0; i < 32; i++) x[i] = sp[32 * i];

        float m = x[0];
        #pragma unroll
        for (int i = 1; i < 32; i++) m = fmaxf(m, x[i]);
        #pragma unroll
        for (int off = 16; off > 0; off >>= 1)
            m = fmaxf(m, __shfl_xor_sync(0xffffffffu, m, off));

        float s = 0.f;
        #pragma unroll
        for (int i = 0; i < 32; i++) { x[i] = __expf(x[i] - m); s += x[i]; }
        #pragma unroll
        for (int off = 16; off > 0; off >>= 1)
            s += __shfl_xor_sync(0xffffffffu, s, off);

        const float inv = 1.0f / s;
        float* go = G + ((size_t)(nt * V_ + vbase + row)) * V_ + lane;
        #pragma unroll
        for (int i = 0; i < 32; i++) go[32 * i] = x[i] * inv;
    }
}

// ============================================================================
extern "C" void kernel_launch(void* const* d_in, const int* in_sizes, int n_in,
                              void* d_out, int out_size)
{
    const float* z  = (const float*)d_in[0];
    const float* tw = (const float*)d_in[1];
    const float* tb = (const float*)d_in[2];
    const float* pw = (const float*)d_in[3];
    const float* pb = (const float*)d_in[4];
    float* G = (float*)d_out;

    proj_kernel<<<dim3(V_ / 64, NT_), 256>>>(z, tw, tb, pw, pb);

    cudaFuncSetAttribute(adj_kernel, cudaFuncAttributeMaxDynamicSharedMemorySize,
                         SMEM2_BYTES);
    adj_kernel<<<NT_ * 32, 256, SMEM2_BYTES>>>(G);
}

// round 3
// speedup vs baseline: 1.2463x; 1.2463x over previous
#include <cuda_runtime.h>
#include <cstdint>

// Problem constants
#define NT_   128      // N*T
#define V_    1024
#define CIN_  256
#define COUT_ 64

// Scratch: theta/phi projections, fp32 (tf32-rounded), stored with k-permuted
// 8-word groups so adj fragment loads are single LDS.64.
__device__ float g_theta[NT_ * V_ * COUT_];
__device__ float g_phi[NT_ * V_ * COUT_];

__device__ __forceinline__ unsigned f2tf(float x) {
    unsigned u;
    asm("cvt.rna.tf32.f32 %0, %1;" : "=r"(u) : "f"(x));
    return u;
}

__device__ __forceinline__ void mma_tf32(float* c,
                                         unsigned a0, unsigned a1, unsigned a2, unsigned a3,
                                         unsigned b0, unsigned b1) {
    asm volatile(
        "mma.sync.aligned.m16n8k8.row.col.f32.tf32.tf32.f32 "
        "{%0,%1,%2,%3},{%4,%5,%6,%7},{%8,%9},{%0,%1,%2,%3};\n"
        : "+f"(c[0]), "+f"(c[1]), "+f"(c[2]), "+f"(c[3])
        : "r"(a0), "r"(a1), "r"(a2), "r"(a3), "r"(b0), "r"(b1));
}

// Permuted position of column k within its 8-word (32B) group: k and k+4
// become adjacent -> fragment (k=t, k=t+4) pair is one 8-byte load.
__device__ __forceinline__ int kperm(int k) {
    return (k & ~7) + ((k & 3) << 1) + ((k >> 2) & 1);
}

__device__ __forceinline__ void cp16(float* dst_smem, const float* src) {
    unsigned d = (unsigned)__cvta_generic_to_shared(dst_smem);
    asm volatile("cp.async.cg.shared.global [%0], [%1], 16;\n" :: "r"(d), "l"(src));
}
__device__ __forceinline__ void cp_commit() {
    asm volatile("cp.async.commit_group;\n");
}
__device__ __forceinline__ void cp_wait0() {
    asm volatile("cp.async.wait_group 0;\n" ::: "memory");
}

// ============================================================================
// Kernel 1: projection (unchanged math from R2; epilogue writes permuted cols).
// ============================================================================
__global__ __launch_bounds__(256) void proj_kernel(
    const float* __restrict__ z, const float* __restrict__ tw,
    const float* __restrict__ tb, const float* __restrict__ pw,
    const float* __restrict__ pb)
{
    __shared__ unsigned As[64 * 36];
    __shared__ unsigned Bs[128 * 36];
    __shared__ float bias_s[128];

    const int tid = threadIdx.x;
    const int nt = blockIdx.y;
    const int vbase = blockIdx.x * 64;

    if (tid < 128) bias_s[tid] = (tid < 64) ? tb[tid] : pb[tid - 64];

    const int wid = tid >> 5, lane = tid & 31;
    const int g = lane >> 2, t = lane & 3;
    const int wm = wid & 3;
    const int wn = wid >> 2;

    float acc[8][4];
    #pragma unroll
    for (int i = 0; i < 8; i++)
        #pragma unroll
        for (int j = 0; j < 4; j++) acc[i][j] = 0.f;

    const float* zb = z + (size_t)(nt * V_ + vbase) * CIN_;

    for (int kc = 0; kc < CIN_; kc += 32) {
        {
            int r = tid >> 3, c4 = (tid & 7) * 4;
            #pragma unroll
            for (int p = 0; p < 2; p++) {
                float4 v = *(const float4*)(zb + (size_t)(r + 32 * p) * CIN_ + kc + c4);
                unsigned* d = &As[(r + 32 * p) * 36 + c4];
                d[0] = f2tf(v.x); d[1] = f2tf(v.y); d[2] = f2tf(v.z); d[3] = f2tf(v.w);
            }
            #pragma unroll
            for (int p = 0; p < 4; p++) {
                int rr = (tid >> 3) + 32 * p;
                const float* src = (rr < 64) ? (tw + (size_t)rr * CIN_)
                                             : (pw + (size_t)(rr - 64) * CIN_);
                float4 v = *(const float4*)(src + kc + c4);
                unsigned* d = &Bs[rr * 36 + c4];
                d[0] = f2tf(v.x); d[1] = f2tf(v.y); d[2] = f2tf(v.z); d[3] = f2tf(v.w);
            }
        }
        __syncthreads();

        #pragma unroll
        for (int ks = 0; ks < 4; ks++) {
            const int k8 = ks * 8;
            unsigned a0 = As[(wm * 16 + g) * 36 + k8 + t];
            unsigned a1 = As[(wm * 16 + g + 8) * 36 + k8 + t];
            unsigned a2 = As[(wm * 16 + g) * 36 + k8 + t + 4];
            unsigned a3 = As[(wm * 16 + g + 8) * 36 + k8 + t + 4];
            #pragma unroll
            for (int nf = 0; nf < 8; nf++) {
                int br = wn * 64 + nf * 8 + g;
                unsigned b0 = Bs[br * 36 + k8 + t];
                unsigned b1 = Bs[br * 36 + k8 + t + 4];
                mma_tf32(acc[nf], a0, a1, a2, a3, b0, b1);
            }
        }
        __syncthreads();
    }

    // Epilogue: bias + write tf32-rounded, k-permuted, theta/phi split.
    const int row0 = vbase + wm * 16 + g;
    #pragma unroll
    for (int nf = 0; nf < 8; nf++) {
        int col = wn * 64 + nf * 8 + 2 * t;   // 0..127
        #pragma unroll
        for (int h = 0; h < 2; h++) {         // col, col+1
            int cc = col + h;
            float bv = bias_s[cc];
            float* dst = (cc < 64) ? g_theta : g_phi;
            int c = (cc < 64) ? cc : cc - 64;
            int cp = kperm(c);
            float v0 = __uint_as_float(f2tf(acc[nf][h] + bv));
            float v1 = __uint_as_float(f2tf(acc[nf][2 + h] + bv));
            dst[((size_t)(nt * V_) + row0) * COUT_ + cp] = v0;
            dst[((size_t)(nt * V_) + row0 + 8) * COUT_ + cp] = v1;
        }
    }
}

// ============================================================================
// Kernel 2: two-pass max-free softmax-GEMM, no Sbuf.
// BM=128 rows/block, BN=64 col chunks x16, 512 threads (4 m-warps x 4 n-warps).
// Pass 1: S=theta.phi^T chunk-wise, exp, row sums. Pass 2: recompute, scale, write.
// ============================================================================
#define SROW     72                      // smem row stride (words), conflict-free LDS.64
#define TS_OFF   0                       // 128*72 = 9216 words
#define PS_OFF   (128 * SROW)            // 2 x 64*72 = 9216 words
#define PS_SZ    (64 * SROW)
#define RED_OFF  (PS_OFF + 2 * PS_SZ)    // 4*128
#define INV_OFF  (RED_OFF + 512)         // 128
#define SMEM_WORDS (INV_OFF + 128)
#define SMEM2_BYTES (SMEM_WORDS * 4)

__global__ void __launch_bounds__(512, 2) adj_kernel(float* __restrict__ G)
{
    extern __shared__ float sm[];
    float* Ts   = sm + TS_OFF;
    float* Ps   = sm + PS_OFF;
    float* red  = sm + RED_OFF;
    float* invs = sm + INV_OFF;

    const int tid = threadIdx.x, lane = tid & 31, wid = tid >> 5;
    const int g = lane >> 2, t = lane & 3;
    const int wm = wid & 3;     // 4 m-warps x 32 rows
    const int wn = wid >> 2;    // 4 n-warps x 16 cols
    const int nt = blockIdx.x >> 3;
    const int vbase = (blockIdx.x & 7) * 128;

    const float* th = g_theta + (size_t)(nt * V_ + vbase) * COUT_;
    const float* ph = g_phi + (size_t)nt * V_ * COUT_;

    // Stage Ts (128x64) + phi chunk 0 via cp.async (one group).
    #pragma unroll
    for (int p = 0; p < 4; p++) {
        int lin = tid + 512 * p;           // 0..2047: 16B chunks of Ts
        int r = lin >> 4, c = lin & 15;
        cp16(&Ts[r * SROW + c * 4], th + (size_t)r * COUT_ + c * 4);
    }
    #pragma unroll
    for (int p = 0; p < 2; p++) {
        int lin = tid + 512 * p;           // 0..1023: 16B chunks of chunk0
        int r = lin >> 4, c = lin & 15;
        cp16(&Ps[r * SROW + c * 4], ph + (size_t)r * COUT_ + c * 4);
    }
    cp_commit();

    float rowsum[4] = {0.f, 0.f, 0.f, 0.f};

    // ---------------- PASS 1: sums ----------------
    for (int cw = 0; cw < 16; cw++) {
        cp_wait0();
        __syncthreads();
        if (cw < 15) {
            float* Pn = Ps + ((cw + 1) & 1) * PS_SZ;
            const float* src = ph + (size_t)(cw + 1) * 64 * COUT_;
            #pragma unroll
            for (int p = 0; p < 2; p++) {
                int lin = tid + 512 * p;
                int r = lin >> 4, c = lin & 15;
                cp16(&Pn[r * SROW + c * 4], src + (size_t)r * COUT_ + c * 4);
            }
            cp_commit();
        }
        float* P = Ps + (cw & 1) * PS_SZ;

        float acc[2][2][4];
        #pragma unroll
        for (int i = 0; i < 2; i++)
            #pragma unroll
            for (int j = 0; j < 2; j++)
                #pragma unroll
                for (int k = 0; k < 4; k++) acc[i][j][k] = 0.f;

        #pragma unroll
        for (int ks = 0; ks < 8; ks++) {
            const int ko = ks * 8 + 2 * t;
            float2 a00 = *(float2*)&Ts[(wm * 32 + g) * SROW + ko];
            float2 a01 = *(float2*)&Ts[(wm * 32 + 8 + g) * SROW + ko];
            float2 a10 = *(float2*)&Ts[(wm * 32 + 16 + g) * SROW + ko];
            float2 a11 = *(float2*)&Ts[(wm * 32 + 24 + g) * SROW + ko];
            float2 b0 = *(float2*)&P[(wn * 16 + g) * SROW + ko];
            float2 b1 = *(float2*)&P[(wn * 16 + 8 + g) * SROW + ko];
            mma_tf32(acc[0][0], __float_as_uint(a00.x), __float_as_uint(a01.x),
                                __float_as_uint(a00.y), __float_as_uint(a01.y),
                                __float_as_uint(b0.x), __float_as_uint(b0.y));
            mma_tf32(acc[0][1], __float_as_uint(a00.x), __float_as_uint(a01.x),
                                __float_as_uint(a00.y), __float_as_uint(a01.y),
                                __float_as_uint(b1.x), __float_as_uint(b1.y));
            mma_tf32(acc[1][0], __float_as_uint(a10.x), __float_as_uint(a11.x),
                                __float_as_uint(a10.y), __float_as_uint(a11.y),
                                __float_as_uint(b0.x), __float_as_uint(b0.y));
            mma_tf32(acc[1][1], __float_as_uint(a10.x), __float_as_uint(a11.x),
                                __float_as_uint(a10.y), __float_as_uint(a11.y),
                                __float_as_uint(b1.x), __float_as_uint(b1.y));
        }
        #pragma unroll
        for (int mf = 0; mf < 2; mf++)
            #pragma unroll
            for (int nf = 0; nf < 2; nf++) {
                rowsum[mf * 2 + 0] += __expf(acc[mf][nf][0]) + __expf(acc[mf][nf][1]);
                rowsum[mf * 2 + 1] += __expf(acc[mf][nf][2]) + __expf(acc[mf][nf][3]);
            }
        __syncthreads();
    }

    // Kick off pass-2 chunk 0 (buf0 is free).
    #pragma unroll
    for (int p = 0; p < 2; p++) {
        int lin = tid + 512 * p;
        int r = lin >> 4, c = lin & 15;
        cp16(&Ps[r * SROW + c * 4], ph + (size_t)r * COUT_ + c * 4);
    }
    cp_commit();

    // Cross-lane (t) and cross-warp (wn) row-sum reduction.
    #pragma unroll
    for (int i = 0; i < 4; i++) {
        float s = rowsum[i];
        s += __shfl_xor_sync(0xffffffffu, s, 1);
        s += __shfl_xor_sync(0xffffffffu, s, 2);
        if (t == 0)
            red[wn * 128 + wm * 32 + (i & 1) * 8 + (i >> 1) * 16 + g] = s;
    }
    __syncthreads();
    if (tid < 128) {
        float s = red[tid] + red[128 + tid] + red[256 + tid] + red[384 + tid];
        invs[tid] = 1.0f / s;
    }
    __syncthreads();

    float inv[4];
    #pragma unroll
    for (int i = 0; i < 4; i++)
        inv[i] = invs[wm * 32 + (i & 1) * 8 + (i >> 1) * 16 + g];

    float* gr = G + (size_t)(nt * V_ + vbase) * V_;

    // ---------------- PASS 2: recompute, normalize, write ----------------
    for (int cw = 0; cw < 16; cw++) {
        cp_wait0();
        __syncthreads();
        if (cw < 15) {
            float* Pn = Ps + ((cw + 1) & 1) * PS_SZ;
            const float* src = ph + (size_t)(cw + 1) * 64 * COUT_;
            #pragma unroll
            for (int p = 0; p < 2; p++) {
                int lin = tid + 512 * p;
                int r = lin >> 4, c = lin & 15;
                cp16(&Pn[r * SROW + c * 4], src + (size_t)r * COUT_ + c * 4);
            }
            cp_commit();
        }
        float* P = Ps + (cw & 1) * PS_SZ;

        float acc[2][2][4];
        #pragma unroll
        for (int i = 0; i < 2; i++)
            #pragma unroll
            for (int j = 0; j < 2; j++)
                #pragma unroll
                for (int k = 0; k < 4; k++) acc[i][j][k] = 0.f;

        #pragma unroll
        for (int ks = 0; ks < 8; ks++) {
            const int ko = ks * 8 + 2 * t;
            float2 a00 = *(float2*)&Ts[(wm * 32 + g) * SROW + ko];
            float2 a01 = *(float2*)&Ts[(wm * 32 + 8 + g) * SROW + ko];
            float2 a10 = *(float2*)&Ts[(wm * 32 + 16 + g) * SROW + ko];
            float2 a11 = *(float2*)&Ts[(wm * 32 + 24 + g) * SROW + ko];
            float2 b0 = *(float2*)&P[(wn * 16 + g) * SROW + ko];
            float2 b1 = *(float2*)&P[(wn * 16 + 8 + g) * SROW + ko];
            mma_tf32(acc[0][0], __float_as_uint(a00.x), __float_as_uint(a01.x),
                                __float_as_uint(a00.y), __float_as_uint(a01.y),
                                __float_as_uint(b0.x), __float_as_uint(b0.y));
            mma_tf32(acc[0][1], __float_as_uint(a00.x), __float_as_uint(a01.x),
                                __float_as_uint(a00.y), __float_as_uint(a01.y),
                                __float_as_uint(b1.x), __float_as_uint(b1.y));
            mma_tf32(acc[1][0], __float_as_uint(a10.x), __float_as_uint(a11.x),
                                __float_as_uint(a10.y), __float_as_uint(a11.y),
                                __float_as_uint(b0.x), __float_as_uint(b0.y));
            mma_tf32(acc[1][1], __float_as_uint(a10.x), __float_as_uint(a11.x),
                                __float_as_uint(a10.y), __float_as_uint(a11.y),
                                __float_as_uint(b1.x), __float_as_uint(b1.y));
        }

        #pragma unroll
        for (int mf = 0; mf < 2; mf++)
            #pragma unroll
            for (int nf = 0; nf < 2; nf++) {
                int col = cw * 64 + wn * 16 + nf * 8 + 2 * t;
                int r0 = wm * 32 + mf * 16 + g;
                float2 v0, v1;
                v0.x = __expf(acc[mf][nf][0]) * inv[mf * 2 + 0];
                v0.y = __expf(acc[mf][nf][1]) * inv[mf * 2 + 0];
                v1.x = __expf(acc[mf][nf][2]) * inv[mf * 2 + 1];
                v1.y = __expf(acc[mf][nf][3]) * inv[mf * 2 + 1];
                *(float2*)&gr[(size_t)r0 * V_ + col] = v0;
                *(float2*)&gr[(size_t)(r0 + 8) * V_ + col] = v1;
            }
        __syncthreads();
    }
}

// ============================================================================
extern "C" void kernel_launch(void* const* d_in, const int* in_sizes, int n_in,
                              void* d_out, int out_size)
{
    const float* z  = (const float*)d_in[0];
    const float* tw = (const float*)d_in[1];
    const float* tb = (const float*)d_in[2];
    const float* pw = (const float*)d_in[3];
    const float* pb = (const float*)d_in[4];
    float* G = (float*)d_out;

    proj_kernel<<<dim3(V_ / 64, NT_), 256>>>(z, tw, tb, pw, pb);

    cudaFuncSetAttribute(adj_kernel, cudaFuncAttributeMaxDynamicSharedMemorySize,
                         SMEM2_BYTES);
    adj_kernel<<<NT_ * 8, 512, SMEM2_BYTES>>>(G);
}

// round 6
// speedup vs baseline: 1.5808x; 1.2684x over previous
#include <cuda_runtime.h>
#include <cuda_fp16.h>
#include <cstdint>

// Problem constants
#define NT_   128      // N*T
#define V_    1024
#define CIN_  256
#define COUT_ 64

// Scratch: theta/phi projections, fp32 (tf32-rounded), row-major [v][64].
__device__ float g_theta[NT_ * V_ * COUT_];
__device__ float g_phi[NT_ * V_ * COUT_];

__device__ __forceinline__ unsigned f2tf(float x) {
    unsigned u;
    asm("cvt.rna.tf32.f32 %0, %1;" : "=r"(u) : "f"(x));
    return u;
}

__device__ __forceinline__ void mma_tf32(float* c,
                                         float a0, float a1, float a2, float a3,
                                         float b0, float b1) {
    asm volatile(
        "mma.sync.aligned.m16n8k8.row.col.f32.tf32.tf32.f32 "
        "{%0,%1,%2,%3},{%4,%5,%6,%7},{%8,%9},{%0,%1,%2,%3};\n"
        : "+f"(c[0]), "+f"(c[1]), "+f"(c[2]), "+f"(c[3])
        : "r"(__float_as_uint(a0)), "r"(__float_as_uint(a1)),
          "r"(__float_as_uint(a2)), "r"(__float_as_uint(a3)),
          "r"(__float_as_uint(b0)), "r"(__float_as_uint(b1)));
}

__device__ __forceinline__ uint32_t smem_u32(const void* p) {
    uint32_t a;
    asm("{ .reg .u64 t; cvta.to.shared.u64 t, %1; cvt.u32.u64 %0, t; }"
        : "=r"(a) : "l"(p));
    return a;
}
__device__ __forceinline__ void cp16s(uint32_t daddr, const float* src) {
    asm volatile("cp.async.cg.shared.global [%0], [%1], 16;\n" :: "r"(daddr), "l"(src));
}
__device__ __forceinline__ void cp_commit() { asm volatile("cp.async.commit_group;\n"); }
__device__ __forceinline__ void cp_wait0() { asm volatile("cp.async.wait_group 0;\n" ::: "memory"); }
__device__ __forceinline__ void cp_wait1() { asm volatile("cp.async.wait_group 1;\n" ::: "memory"); }

// ============================================================================
// Kernel 1: projection. Block: 64 v-rows x 128 out-cols (theta|phi), 256 thr.
// cp.async double-buffered 32-k chunks; raw-fp32 tf32 operands (HW truncation).
// Warps: wm = wid&3 (16 rows), wn = wid>>2 (64 cols = theta or phi entirely).
// ============================================================================
#define PJ_SR     40                       // smem row stride (words) per 32-k chunk
#define PJ_A_SZ   (64 * PJ_SR)             // words
#define PJ_B_SZ   (128 * PJ_SR)
#define PJ_BUF    (PJ_A_SZ + PJ_B_SZ)
#define PJ_SMEM_BYTES (2 * PJ_BUF * 4)

__global__ void __launch_bounds__(256, 2) proj_kernel(
    const float* __restrict__ z, const float* __restrict__ tw,
    const float* __restrict__ tb, const float* __restrict__ pw,
    const float* __restrict__ pb)
{
    extern __shared__ float psm[];
    __shared__ float bias_s[128];

    const int tid = threadIdx.x, lane = tid & 31, wid = tid >> 5;
    const int g = lane >> 2, t = lane & 3;
    const int wm = wid & 3, wn = wid >> 2;
    const int nt = blockIdx.y;
    const int vbase = blockIdx.x * 64;

    if (tid < 128) bias_s[tid] = (tid < 64) ? tb[tid] : pb[tid - 64];

    const float* zb = z + (size_t)(nt * V_ + vbase) * CIN_;
    const uint32_t sb = smem_u32(psm);

    // stage chunk c into buffer b: A = z[64 x 32], B = Wcat[128 x 32]
    auto stage = [&](int c, int b) {
        const uint32_t ab = sb + (uint32_t)(b * PJ_BUF) * 4u;
        const uint32_t bb = ab + (uint32_t)PJ_A_SZ * 4u;
        const int kc = c * 32;
        #pragma unroll
        for (int p = 0; p < 2; p++) {
            int lin = tid + 256 * p;          // 0..511: A 16B chunks
            int r = lin >> 3, c8 = lin & 7;
            cp16s(ab + (uint32_t)(r * PJ_SR * 4 + c8 * 16),
                  zb + (size_t)r * CIN_ + kc + c8 * 4);
        }
        #pragma unroll
        for (int p = 0; p < 4; p++) {
            int lin = tid + 256 * p;          // 0..1023: B 16B chunks
            int r = lin >> 3, c8 = lin & 7;
            const float* src = (r < 64) ? (tw + (size_t)r * CIN_)
                                        : (pw + (size_t)(r - 64) * CIN_);
            cp16s(bb + (uint32_t)(r * PJ_SR * 4 + c8 * 16), src + kc + c8 * 4);
        }
        cp_commit();
    };

    float acc[8][4];
    #pragma unroll
    for (int i = 0; i < 8; i++)
        #pragma unroll
        for (int j = 0; j < 4; j++) acc[i][j] = 0.f;

    stage(0, 0);
    for (int c = 0; c < 8; c++) {
        if (c < 7) stage(c + 1, (c + 1) & 1);
        if (c < 7) cp_wait1(); else cp_wait0();
        __syncthreads();
        const float* A = psm + (c & 1) * PJ_BUF;
        const float* B = A + PJ_A_SZ;

        #pragma unroll
        for (int ks = 0; ks < 4; ks++) {
            const int ko = ks * 8 + 2 * t;
            float2 ar0 = *(const float2*)&A[(wm * 16 + g) * PJ_SR + ko];
            float2 ar1 = *(const float2*)&A[(wm * 16 + 8 + g) * PJ_SR + ko];
            #pragma unroll
            for (int nf = 0; nf < 8; nf++) {
                float2 bf = *(const float2*)&B[(wn * 64 + nf * 8 + g) * PJ_SR + ko];
                mma_tf32(acc[nf], ar0.x, ar1.x, ar0.y, ar1.y, bf.x, bf.y);
            }
        }
        __syncthreads();
    }

    // Epilogue: bias, tf32-round, float2 stores. wn=0 -> theta, wn=1 -> phi.
    float* dst = wn ? g_phi : g_theta;
    const int row0 = vbase + wm * 16 + g;
    #pragma unroll
    for (int nf = 0; nf < 8; nf++) {
        int c = nf * 8 + 2 * t;
        float b0 = bias_s[wn * 64 + c], b1 = bias_s[wn * 64 + c + 1];
        float2 v0 = make_float2(__uint_as_float(f2tf(acc[nf][0] + b0)),
                                __uint_as_float(f2tf(acc[nf][1] + b1)));
        float2 v1 = make_float2(__uint_as_float(f2tf(acc[nf][2] + b0)),
                                __uint_as_float(f2tf(acc[nf][3] + b1)));
        *(float2*)&dst[((size_t)(nt * V_) + row0) * COUT_ + c] = v0;
        *(float2*)&dst[((size_t)(nt * V_) + row0 + 8) * COUT_ + c] = v1;
    }
}

// ============================================================================
// Kernel 2: single-exp softmax-GEMM.
// Block: 64 theta rows x 1024 cols, 512 threads (2 m-warps x 8 n-warps).
// Theta fragments in REGISTERS (zero A-side LDS).
// Pass 1: per 128-col chunk, S via mma -> exp -> fp16 E-buffer + fp32 rowsums.
// Pass 2: read E, scale by 1/sum, write G. No recompute, exp once per element.
// SMEM: E 64x520 u32 (133KB) + phi double buf 2x128x72 f32 (72KB) = 206.8KB.
// ============================================================================
#define ESTRIDE  520                       // u32 words per row (1040 fp16)
#define BSR      72                        // phi buf row stride (words)
#define PBUF_W   (128 * BSR)
#define ADJ_SMEM_BYTES ((64 * ESTRIDE + 2 * PBUF_W) * 4)

__global__ void __launch_bounds__(512, 1) adj_kernel(float* __restrict__ G)
{
    extern __shared__ unsigned asm_[];
    unsigned* E = asm_;                         // 64 x ESTRIDE
    float* P = (float*)(asm_ + 64 * ESTRIDE);   // 2 x 128 x BSR
    __shared__ float red[512];
    __shared__ float invs[64];

    const int tid = threadIdx.x, lane = tid & 31, wid = tid >> 5;
    const int g = lane >> 2, t = lane & 3;
    const int wm = wid & 1;     // 2 m-warps x 32 rows
    const int wn = wid >> 1;    // 8 n-warps x 16 cols (per 128-col chunk)
    const int nt = blockIdx.x >> 4;
    const int vbase = (blockIdx.x & 15) * 64;

    const float* th = g_theta + (size_t)(nt * V_ + vbase) * COUT_;
    const float* ph = g_phi + (size_t)nt * V_ * COUT_;
    const uint32_t pbase = smem_u32(P);

    // ---- theta fragments -> registers: a[mf][h][ks] = rows wm*32+mf*16+g+8h
    float2 a[2][2][8];
    #pragma unroll
    for (int mf = 0; mf < 2; mf++)
        #pragma unroll
        for (int h = 0; h < 2; h++)
            #pragma unroll
            for (int ks = 0; ks < 8; ks++)
                a[mf][h][ks] = *(const float2*)&th[
                    (size_t)(wm * 32 + mf * 16 + g + 8 * h) * COUT_ + ks * 8 + 2 * t];

    auto stage = [&](int c, int b) {
        const uint32_t dst = pbase + (uint32_t)(b * PBUF_W) * 4u;
        const float* src = ph + (size_t)c * 128 * COUT_;
        #pragma unroll
        for (int p = 0; p < 4; p++) {
            int lin = tid + 512 * p;          // 0..2047
            int r = lin >> 4, c4 = lin & 15;
            cp16s(dst + (uint32_t)(r * BSR * 4 + c4 * 16),
                  src + (size_t)r * COUT_ + c4 * 4);
        }
        cp_commit();
    };

    stage(0, 0);
    float rowsum[4] = {0.f, 0.f, 0.f, 0.f};

    // ---------------- PASS 1 ----------------
    for (int c = 0; c < 8; c++) {
        if (c < 7) stage(c + 1, (c + 1) & 1);
        if (c < 7) cp_wait1(); else cp_wait0();
        __syncthreads();
        const float* B = P + (c & 1) * PBUF_W;

        float acc[2][2][4];
        #pragma unroll
        for (int i = 0; i < 2; i++)
            #pragma unroll
            for (int j = 0; j < 2; j++)
                #pragma unroll
                for (int k = 0; k < 4; k++) acc[i][j][k] = 0.f;

        #pragma unroll
        for (int ks = 0; ks < 8; ks++) {
            const int ko = ks * 8 + 2 * t;
            float2 b0 = *(const float2*)&B[(wn * 16 + g) * BSR + ko];
            float2 b1 = *(const float2*)&B[(wn * 16 + 8 + g) * BSR + ko];
            #pragma unroll
            for (int mf = 0; mf < 2; mf++) {
                mma_tf32(acc[mf][0], a[mf][0][ks].x, a[mf][1][ks].x,
                         a[mf][0][ks].y, a[mf][1][ks].y, b0.x, b0.y);
                mma_tf32(acc[mf][1], a[mf][0][ks].x, a[mf][1][ks].x,
                         a[mf][0][ks].y, a[mf][1][ks].y, b1.x, b1.y);
            }
        }

        // exp + fp16 store + rowsums
        #pragma unroll
        for (int mf = 0; mf < 2; mf++)
            #pragma unroll
            for (int nf = 0; nf < 2; nf++) {
                float e0 = __expf(acc[mf][nf][0]);
                float e1 = __expf(acc[mf][nf][1]);
                float e2 = __expf(acc[mf][nf][2]);
                float e3 = __expf(acc[mf][nf][3]);
                rowsum[mf * 2 + 0] += e0 + e1;
                rowsum[mf * 2 + 1] += e2 + e3;
                int col2 = c * 64 + wn * 8 + nf * 4 + t;
                int r0 = wm * 32 + mf * 16 + g;
                __half2 h0 = __floats2half2_rn(e0, e1);
                __half2 h1 = __floats2half2_rn(e2, e3);
                E[r0 * ESTRIDE + col2] = *(unsigned*)&h0;
                E[(r0 + 8) * ESTRIDE + col2] = *(unsigned*)&h1;
            }
        __syncthreads();
    }

    // ---------------- row-sum reduction ----------------
    #pragma unroll
    for (int i = 0; i < 4; i++) {
        float s = rowsum[i];
        s += __shfl_xor_sync(0xffffffffu, s, 1);
        s += __shfl_xor_sync(0xffffffffu, s, 2);
        if (t == 0)
            red[wn * 64 + wm * 32 + (i >> 1) * 16 + (i & 1) * 8 + g] = s;
    }
    __syncthreads();
    if (tid < 64) {
        float s = 0.f;
        #pragma unroll
        for (int w = 0; w < 8; w++) s += red[w * 64 + tid];
        invs[tid] = 1.0f / s;
    }
    __syncthreads();

    // ---------------- PASS 2: scale + write ----------------
    const int row = tid >> 3;
    const int c2b = tid & 7;
    const float iv = invs[row];
    float* grow = G + ((size_t)(nt * V_ + vbase + row)) * V_;
    const unsigned* er = E + row * ESTRIDE;
    #pragma unroll 8
    for (int j = 0; j < 64; j++) {
        unsigned u = er[c2b + 8 * j];
        float2 f = __half22float2(*(__half2*)&u);
        f.x *= iv; f.y *= iv;
        *(float2*)&grow[2 * (c2b + 8 * j)] = f;
    }
}

// ============================================================================
extern "C" void kernel_launch(void* const* d_in, const int* in_sizes, int n_in,
                              void* d_out, int out_size)
{
    const float* z  = (const float*)d_in[0];
    const float* tw = (const float*)d_in[1];
    const float* tb = (const float*)d_in[2];
    const float* pw = (const float*)d_in[3];
    const float* pb = (const float*)d_in[4];
    float* G = (float*)d_out;

    cudaFuncSetAttribute(proj_kernel, cudaFuncAttributeMaxDynamicSharedMemorySize,
                         PJ_SMEM_BYTES);
    proj_kernel<<<dim3(V_ / 64, NT_), 256, PJ_SMEM_BYTES>>>(z, tw, tb, pw, pb);

    cudaFuncSetAttribute(adj_kernel, cudaFuncAttributeMaxDynamicSharedMemorySize,
                         ADJ_SMEM_BYTES);
    adj_kernel<<<NT_ * 16, 512, ADJ_SMEM_BYTES>>>(G);
}